// round 6
// baseline (speedup 1.0000x reference)
#include <cuda_runtime.h>

// RWKV v4 single-token forward, persistent kernel, round 6.
// Key change vs R5: each warp's next-stage GEMV weights are staged into
// per-warp shared-memory slots with cp.async, issued BEFORE the grid barrier.
// DRAM streaming thus overlaps barrier wait + elementwise phases; the dot
// products consume from smem. T=768 (24 warps) to fit 2x4KB slots per warp.

#define E    1024
#define HH   4096
#define NL   24
#define NV   50277
#define T    768
#define WPB  24

// ---- persistent device scratch ----
__device__ float g_kvr[3 * E];
__device__ float g_op[2][E];
__device__ float g_fk[HH];
__device__ float g_frp[2][E];
__device__ float g_fvp[4][E];
__device__ unsigned int g_bar[2];   // {count, generation}; memset per launch

struct P {
    const float *ctx, *state, *ln0w, *ln0b, *ln1w, *ln1b, *ln2w, *ln2b;
    const float *td, *tf, *tmk, *tmv, *tmr, *kw, *vw, *rw, *ow;
    const float *ftmk, *ftmr, *fkw, *frw, *fvw, *lnoutw, *lnoutb, *head;
    float* out;
    int nb;
    int ws;
};

__device__ __forceinline__ void grid_sync(int nb) {
    __syncthreads();
    if (threadIdx.x == 0) {
        unsigned int gen = ((volatile unsigned int*)g_bar)[1];
        __threadfence();
        if (atomicAdd(&g_bar[0], 1u) == (unsigned int)(nb - 1)) {
            atomicExch(&g_bar[0], 0u);
            __threadfence();
            atomicAdd(&g_bar[1], 1u);
        } else {
            while (((volatile unsigned int*)g_bar)[1] == gen) { __nanosleep(64); }
        }
        __threadfence();
    }
    __syncthreads();
}

__device__ __forceinline__ void block_reduce2(float& a, float& b, float* sr) {
    #pragma unroll
    for (int o = 16; o; o >>= 1) {
        a += __shfl_down_sync(0xFFFFFFFFu, a, o);
        b += __shfl_down_sync(0xFFFFFFFFu, b, o);
    }
    int w = threadIdx.x >> 5, l = threadIdx.x & 31;
    __syncthreads();
    if (l == 0) { sr[w] = a; sr[w + WPB] = b; }
    __syncthreads();
    if (threadIdx.x == 0) {
        float sa = 0.f, sb2 = 0.f;
        #pragma unroll
        for (int i = 0; i < WPB; i++) { sa += sr[i]; sb2 += sr[i + WPB]; }
        sr[2 * WPB] = sa; sr[2 * WPB + 1] = sb2;
    }
    __syncthreads();
    a = sr[2 * WPB];
    b = sr[2 * WPB + 1];
}

// global-memory warp dot (head GEMV), read-once weights
template <int N4>
__device__ __forceinline__ float warp_dot(const float* __restrict__ w,
                                          const float* x, int lane) {
    const float4* __restrict__ w4 = (const float4*)w;
    const float4* x4 = (const float4*)x;
    float a0 = 0.f, a1 = 0.f, a2 = 0.f, a3 = 0.f;
    #pragma unroll
    for (int u = 0; u < N4; u += 4) {
        float4 wa = __ldcs(&w4[lane + 32 * u]);
        float4 xa = x4[lane + 32 * u];
        a0 += wa.x * xa.x + wa.y * xa.y + wa.z * xa.z + wa.w * xa.w;
        float4 wb = __ldcs(&w4[lane + 32 * (u + 1)]);
        float4 xb = x4[lane + 32 * (u + 1)];
        a1 += wb.x * xb.x + wb.y * xb.y + wb.z * xb.z + wb.w * xb.w;
        float4 wc = __ldcs(&w4[lane + 32 * (u + 2)]);
        float4 xc = x4[lane + 32 * (u + 2)];
        a2 += wc.x * xc.x + wc.y * xc.y + wc.z * xc.z + wc.w * xc.w;
        float4 wd = __ldcs(&w4[lane + 32 * (u + 3)]);
        float4 xd = x4[lane + 32 * (u + 3)];
        a3 += wd.x * xd.x + wd.y * xd.y + wd.z * xd.z + wd.w * xd.w;
    }
    float acc = (a0 + a1) + (a2 + a3);
    #pragma unroll
    for (int o = 16; o; o >>= 1) acc += __shfl_down_sync(0xFFFFFFFFu, acc, o);
    return acc;
}

// smem-slot warp dot (weights already staged)
template <int N4>
__device__ __forceinline__ float dot_slot(const float* w, const float* x, int lane) {
    const float4* w4 = (const float4*)w;
    const float4* x4 = (const float4*)x;
    float a0 = 0.f, a1 = 0.f, a2 = 0.f, a3 = 0.f;
    #pragma unroll
    for (int u = 0; u < N4; u += 4) {
        float4 wa = w4[lane + 32 * u];       float4 xa = x4[lane + 32 * u];
        a0 += wa.x * xa.x + wa.y * xa.y + wa.z * xa.z + wa.w * xa.w;
        if (u + 1 < N4) { float4 wb = w4[lane + 32 * (u + 1)]; float4 xb = x4[lane + 32 * (u + 1)];
            a1 += wb.x * xb.x + wb.y * xb.y + wb.z * xb.z + wb.w * xb.w; }
        if (u + 2 < N4) { float4 wc = w4[lane + 32 * (u + 2)]; float4 xc = x4[lane + 32 * (u + 2)];
            a2 += wc.x * xc.x + wc.y * xc.y + wc.z * xc.z + wc.w * xc.w; }
        if (u + 3 < N4) { float4 wd = w4[lane + 32 * (u + 3)]; float4 xd = x4[lane + 32 * (u + 3)];
            a3 += wd.x * xd.x + wd.y * xd.y + wd.z * xd.z + wd.w * xd.w; }
    }
    float acc = (a0 + a1) + (a2 + a3);
    #pragma unroll
    for (int o = 16; o; o >>= 1) acc += __shfl_down_sync(0xFFFFFFFFu, acc, o);
    return acc;
}

__device__ __forceinline__ void cpa16(float* smem_dst, const float* g) {
    unsigned saddr = (unsigned)__cvta_generic_to_shared(smem_dst);
    asm volatile("cp.async.cg.shared.global [%0], [%1], 16;" :: "r"(saddr), "l"(g));
}

// stage weights into this warp's slot: n4 16B chunks per lane
__device__ __forceinline__ void preload_task(float* dst, const float* src, int lane, int n4) {
    #pragma unroll
    for (int j = 0; j < 8; j++)
        if (j < n4) cpa16(dst + ((lane + 32 * j) << 2), src + ((lane + 32 * j) << 2));
}

#define CP_COMMIT() asm volatile("cp.async.commit_group;" ::: "memory")
#define CP_WAIT()   asm volatile("cp.async.wait_group 0;" ::: "memory")

// smem: sx[E] + sop[HH] + sred[64] + slots[WPB*2*1024]
#define SMEM_FLOATS (E + HH + 64 + WPB * 2 * 1024)

__global__ void __launch_bounds__(T, 1) rwkv_kernel(P p) {
    extern __shared__ float smem[];
    float* sx    = smem;
    float* sop   = smem + E;
    float* sred  = smem + E + HH;
    float* slots = smem + E + HH + 64;

    const int tid = threadIdx.x, lane = tid & 31, warp = tid >> 5;
    const int gw = blockIdx.x * WPB + warp;
    const int NW = p.nb * WPB;
    const bool w0 = (p.ws && blockIdx.x == 0);
    float* outS = p.out + NV;
    float* sl0 = slots + warp * 2048;
    float* sl1 = sl0 + 1024;

    // ---- preload layer-0 kvr rows, then LN0 (streams during LN0) ----
    if (gw < 3072) {
        int m = gw >> 10, i = gw & 1023;
        const float* W = (m == 0 ? p.kw : (m == 1 ? p.vw : p.rw)) + (size_t)i * E;
        preload_task(sl0, W, lane, 8);
    }
    CP_COMMIT();

    float s = 0.f, s2 = 0.f;
    for (int i = tid; i < E; i += T) { float v = p.ctx[i]; sx[i] = v; s += v; s2 += v * v; }
    block_reduce2(s, s2, sred);
    {
        float mu = s * (1.f / E);
        float rs = rsqrtf(s2 * (1.f / E) - mu * mu + 1e-5f);
        for (int i = tid; i < E; i += T)
            sx[i] = (sx[i] - mu) * rs * __ldg(p.ln0w + i) + __ldg(p.ln0b + i);
    }
    __syncthreads();

    for (int l = 0; l < NL; l++) {
        const float* st = p.state + (size_t)l * 5 * E;

        // ======== Stage A: combine prev FFN + LN1 + time-mix; consume kvr ========
        if (l > 0) {
            for (int i = tid; i < E; i += T) {
                float fr = 1.f / (1.f + __expf(-(g_frp[0][i] + g_frp[1][i])));
                sx[i] += fr * (g_fvp[0][i] + g_fvp[1][i] + g_fvp[2][i] + g_fvp[3][i]);
            }
        }
        s = 0.f; s2 = 0.f;
        for (int i = tid; i < E; i += T) { float v = sx[i]; s += v; s2 += v * v; }
        block_reduce2(s, s2, sred);
        {
            float mu = s * (1.f / E);
            float rs = rsqrtf(s2 * (1.f / E) - mu * mu + 1e-5f);
            for (int i = tid; i < E; i += T) {
                float xn = (sx[i] - mu) * rs * __ldg(p.ln1w + l * E + i) + __ldg(p.ln1b + l * E + i);
                float spv = __ldg(st + E + i);
                float a = __ldg(p.tmk + l * E + i), b = __ldg(p.tmv + l * E + i), c = __ldg(p.tmr + l * E + i);
                sop[i]         = xn * a + spv * (1.f - a);
                sop[E + i]     = xn * b + spv * (1.f - b);
                sop[2 * E + i] = xn * c + spv * (1.f - c);
                if (w0) outS[(size_t)(5 * l + 1) * E + i] = xn;
            }
        }
        __syncthreads();
        CP_WAIT();
        if (gw < 3072) {
            int m = gw >> 10;
            float acc = dot_slot<8>(sl0, sop + (m << 10), lane);
            if (lane == 0) g_kvr[gw] = acc;
        }
        // preload stage B (ow halves)
        if (gw < 2048) {
            int h = gw & 1, i = gw >> 1;
            preload_task(sl0, p.ow + (size_t)l * E * E + (size_t)i * E + h * 512, lane, 4);
        }
        CP_COMMIT();
        grid_sync(p.nb);

        // ======== Stage B: WKV elementwise; consume ow ========
        {
            for (int i = tid; i < E; i += T) {
                float k  = g_kvr[i];
                float v  = g_kvr[E + i];
                float rr = g_kvr[2 * E + i];
                float A = __ldg(st + 2 * E + i), B = __ldg(st + 3 * E + i), Pp = __ldg(st + 4 * E + i);
                float ww = __ldg(p.tf + l * E + i) + k;
                float q = fmaxf(Pp, ww);
                float e1 = __expf(Pp - q), e2 = __expf(ww - q);
                float num = e1 * A + e2 * v, den = e1 * B + e2;
                float r = 1.f / (1.f + __expf(-rr));
                sop[i] = r * num / den;
                if (w0) {
                    float ww2 = Pp + __ldg(p.td + l * E + i);
                    float p2 = fmaxf(ww2, k);
                    float e1b = __expf(ww2 - p2), e2b = __expf(k - p2);
                    outS[(size_t)(5 * l + 2) * E + i] = e1b * A + e2b * v;
                    outS[(size_t)(5 * l + 3) * E + i] = e1b * B + e2b;
                    outS[(size_t)(5 * l + 4) * E + i] = p2;
                }
            }
        }
        __syncthreads();
        CP_WAIT();
        if (gw < 2048) {
            int h = gw & 1, i = gw >> 1;
            float acc = dot_slot<4>(sl0, sop + h * 512, lane);
            if (lane == 0) g_op[h][i] = acc;
        }
        // preload stage C (fk whole rows t<4096; fr halves 4096..6144)
        {
            const float* FK = p.fkw + (size_t)l * HH * E;
            const float* FR = p.frw + (size_t)l * E * E;
            int t0 = gw;
            if (t0 < 4096) preload_task(sl0, FK + (size_t)t0 * E, lane, 8);
            else if (t0 < 6144) { int ft = t0 - 4096, h = ft & 1, i = ft >> 1;
                preload_task(sl0, FR + (size_t)i * E + h * 512, lane, 4); }
            int t1 = gw + NW;
            if (t1 < 4096) preload_task(sl1, FK + (size_t)t1 * E, lane, 8);
            else if (t1 < 6144) { int ft = t1 - 4096, h = ft & 1, i = ft >> 1;
                preload_task(sl1, FR + (size_t)i * E + h * 512, lane, 4); }
        }
        CP_COMMIT();
        grid_sync(p.nb);

        // ======== Stage C: x += ow; LN2 + chan-mix; consume fk/fr ========
        for (int i = tid; i < E; i += T) sx[i] += g_op[0][i] + g_op[1][i];
        s = 0.f; s2 = 0.f;
        for (int i = tid; i < E; i += T) { float v = sx[i]; s += v; s2 += v * v; }
        block_reduce2(s, s2, sred);
        {
            float mu = s * (1.f / E);
            float rs = rsqrtf(s2 * (1.f / E) - mu * mu + 1e-5f);
            for (int i = tid; i < E; i += T) {
                float xn2 = (sx[i] - mu) * rs * __ldg(p.ln2w + l * E + i) + __ldg(p.ln2b + l * E + i);
                float sv = __ldg(st + i);
                float a = __ldg(p.ftmk + l * E + i), b = __ldg(p.ftmr + l * E + i);
                sop[i]     = xn2 * a + sv * (1.f - a);
                sop[E + i] = xn2 * b + sv * (1.f - b);
                if (w0) outS[(size_t)(5 * l + 0) * E + i] = xn2;
            }
        }
        __syncthreads();
        CP_WAIT();
        {
            int t0 = gw;
            if (t0 < 4096) {
                float acc = dot_slot<8>(sl0, sop, lane);
                if (lane == 0) g_fk[t0] = acc;
            } else if (t0 < 6144) {
                int ft = t0 - 4096, h = ft & 1, i = ft >> 1;
                float acc = dot_slot<4>(sl0, sop + E + h * 512, lane);
                if (lane == 0) g_frp[h][i] = acc;
            }
            int t1 = gw + NW;
            if (t1 < 4096) {
                float acc = dot_slot<8>(sl1, sop, lane);
                if (lane == 0) g_fk[t1] = acc;
            } else if (t1 < 6144) {
                int ft = t1 - 4096, h = ft & 1, i = ft >> 1;
                float acc = dot_slot<4>(sl1, sop + E + h * 512, lane);
                if (lane == 0) g_frp[h][i] = acc;
            }
        }
        // preload stage D (fv quarter rows)
        {
            const float* FV = p.fvw + (size_t)l * E * HH;
            int t0 = gw;
            if (t0 < 4096) { int c = t0 & 3, i = t0 >> 2;
                preload_task(sl0, FV + (size_t)i * HH + c * E, lane, 8); }
            int t1 = gw + NW;
            if (t1 < 4096) { int c = t1 & 3, i = t1 >> 2;
                preload_task(sl1, FV + (size_t)i * HH + c * E, lane, 8); }
        }
        CP_COMMIT();
        grid_sync(p.nb);

        // ======== Stage D: kk = relu^2(fk); consume fv ========
        for (int i = tid; i < HH; i += T) {
            float a = fmaxf(g_fk[i], 0.f);
            sop[i] = a * a;
        }
        __syncthreads();
        CP_WAIT();
        {
            int t0 = gw;
            if (t0 < 4096) { int c = t0 & 3, i = t0 >> 2;
                float acc = dot_slot<8>(sl0, sop + c * E, lane);
                if (lane == 0) g_fvp[c][i] = acc; }
            int t1 = gw + NW;
            if (t1 < 4096) { int c = t1 & 3, i = t1 >> 2;
                float acc = dot_slot<8>(sl1, sop + c * E, lane);
                if (lane == 0) g_fvp[c][i] = acc; }
        }
        // preload next layer's kvr rows
        if (l + 1 < NL && gw < 3072) {
            int m = gw >> 10, i = gw & 1023;
            const float* W = (m == 0 ? p.kw : (m == 1 ? p.vw : p.rw)) + (size_t)(l + 1) * E * E + (size_t)i * E;
            preload_task(sl0, W, lane, 8);
        }
        CP_COMMIT();
        grid_sync(p.nb);
    }

    // ======== final: combine last FFN, LN_out, head GEMV ========
    for (int i = tid; i < E; i += T) {
        float fr = 1.f / (1.f + __expf(-(g_frp[0][i] + g_frp[1][i])));
        sx[i] += fr * (g_fvp[0][i] + g_fvp[1][i] + g_fvp[2][i] + g_fvp[3][i]);
    }
    s = 0.f; s2 = 0.f;
    for (int i = tid; i < E; i += T) { float v = sx[i]; s += v; s2 += v * v; }
    block_reduce2(s, s2, sred);
    {
        float mu = s * (1.f / E);
        float rs = rsqrtf(s2 * (1.f / E) - mu * mu + 1e-5f);
        for (int i = tid; i < E; i += T)
            sop[i] = (sx[i] - mu) * rs * __ldg(p.lnoutw + i) + __ldg(p.lnoutb + i);
    }
    __syncthreads();
    for (int t = gw; t < NV; t += NW) {
        float acc = warp_dot<8>(p.head + (size_t)t * E, sop, lane);
        if (lane == 0) p.out[t] = acc;
    }
}

extern "C" void kernel_launch(void* const* d_in, const int* in_sizes, int n_in,
                              void* d_out, int out_size) {
    (void)in_sizes; (void)n_in;
    P p;
    p.ctx    = (const float*)d_in[0];
    p.state  = (const float*)d_in[1];
    p.ln0w   = (const float*)d_in[2];
    p.ln0b   = (const float*)d_in[3];
    p.ln1w   = (const float*)d_in[4];
    p.ln1b   = (const float*)d_in[5];
    p.ln2w   = (const float*)d_in[6];
    p.ln2b   = (const float*)d_in[7];
    p.td     = (const float*)d_in[8];
    p.tf     = (const float*)d_in[9];
    p.tmk    = (const float*)d_in[10];
    p.tmv    = (const float*)d_in[11];
    p.tmr    = (const float*)d_in[12];
    p.kw     = (const float*)d_in[13];
    p.vw     = (const float*)d_in[14];
    p.rw     = (const float*)d_in[15];
    p.ow     = (const float*)d_in[16];
    p.ftmk   = (const float*)d_in[17];
    p.ftmr   = (const float*)d_in[18];
    p.fkw    = (const float*)d_in[19];
    p.frw    = (const float*)d_in[20];
    p.fvw    = (const float*)d_in[21];
    p.lnoutw = (const float*)d_in[22];
    p.lnoutb = (const float*)d_in[23];
    p.head   = (const float*)d_in[24];
    p.out    = (float*)d_out;

    int dev = 0;
    cudaGetDevice(&dev);
    int nsm = 0;
    cudaDeviceGetAttribute(&nsm, cudaDevAttrMultiProcessorCount, dev);
    if (nsm <= 0) nsm = 148;
    if (nsm > 256) nsm = 256;
    p.nb = nsm;
    p.ws = (out_size >= NV + 5 * NL * E) ? 1 : 0;

    cudaFuncSetAttribute(rwkv_kernel, cudaFuncAttributeMaxDynamicSharedMemorySize,
                         SMEM_FLOATS * sizeof(float));

    void* baddr = nullptr;
    cudaGetSymbolAddress(&baddr, g_bar);
    cudaMemsetAsync(baddr, 0, sizeof(unsigned int) * 2, 0);

    rwkv_kernel<<<nsm, T, SMEM_FLOATS * sizeof(float)>>>(p);
}

// round 7
// speedup vs baseline: 1.1111x; 1.1111x over previous
#include <cuda_runtime.h>

// RWKV v4 single-token forward, persistent kernel, round 7.
// Base = R5 (best). Changes: (1) stage B ow GEMV as quarter-rows (4096 tasks,
// 84% warp utilization vs 42%); (2) stage C fr GEMV as quarter-rows on warps
// [768,4864) with loads issued before the fk dot (concurrent exposures, max
// warp load 5KB vs 8KB); (3) head GEMV processes 2 rows/iteration with
// interleaved loads (2x in-flight work).

#define E    1024
#define HH   4096
#define NL   24
#define NV   50277
#define T    1024
#define WPB  32
#define NPAR 16

// ---- persistent device scratch ----
__device__ float g_kvr[3 * E];     // k, v, r (whole rows)
__device__ float g_op4[4][E];      // ow quarter-row partials
__device__ float g_fk[HH];         // ffn_k pre-relu (whole rows)
__device__ float g_fr4[4][E];      // ffn_r quarter-row partials
__device__ float g_fvp[4][E];      // ffn_v quarter-row partials
__device__ unsigned int g_bar[2];  // {count, generation}; memset per launch

struct P {
    const float *ctx, *state, *ln0w, *ln0b, *ln1w, *ln1b, *ln2w, *ln2b;
    const float *td, *tf, *tmk, *tmv, *tmr, *kw, *vw, *rw, *ow;
    const float *ftmk, *ftmr, *fkw, *frw, *fvw, *lnoutw, *lnoutb, *head;
    float* out;
    int nb;
    int ws;
};

__device__ __forceinline__ void grid_sync(int nb) {
    __syncthreads();
    if (threadIdx.x == 0) {
        unsigned int gen = ((volatile unsigned int*)g_bar)[1];
        __threadfence();
        if (atomicAdd(&g_bar[0], 1u) == (unsigned int)(nb - 1)) {
            atomicExch(&g_bar[0], 0u);
            __threadfence();
            atomicAdd(&g_bar[1], 1u);
        } else {
            while (((volatile unsigned int*)g_bar)[1] == gen) { __nanosleep(64); }
        }
        __threadfence();
    }
    __syncthreads();
}

__device__ __forceinline__ void block_reduce2(float& a, float& b, float* sr) {
    #pragma unroll
    for (int o = 16; o; o >>= 1) {
        a += __shfl_down_sync(0xFFFFFFFFu, a, o);
        b += __shfl_down_sync(0xFFFFFFFFu, b, o);
    }
    int w = threadIdx.x >> 5, l = threadIdx.x & 31;
    __syncthreads();
    if (l == 0) { sr[w] = a; sr[w + WPB] = b; }
    __syncthreads();
    if (threadIdx.x == 0) {
        float sa = 0.f, sb2 = 0.f;
        #pragma unroll
        for (int i = 0; i < WPB; i++) { sa += sr[i]; sb2 += sr[i + WPB]; }
        sr[2 * WPB] = sa; sr[2 * WPB + 1] = sb2;
    }
    __syncthreads();
    a = sr[2 * WPB];
    b = sr[2 * WPB + 1];
}

// warp dot over 128*N4 floats; weights streamed with .cs (read-once)
template <int N4>
__device__ __forceinline__ float warp_dot(const float* __restrict__ w,
                                          const float* x, int lane) {
    const float4* __restrict__ w4 = (const float4*)w;
    const float4* x4 = (const float4*)x;
    float a0 = 0.f, a1 = 0.f, a2 = 0.f, a3 = 0.f;
    #pragma unroll
    for (int u = 0; u < N4; u += 4) {
        float4 wa = __ldcs(&w4[lane + 32 * u]);
        float4 xa = x4[lane + 32 * u];
        a0 += wa.x * xa.x + wa.y * xa.y + wa.z * xa.z + wa.w * xa.w;
        if (u + 1 < N4) {
            float4 wb = __ldcs(&w4[lane + 32 * (u + 1)]);
            float4 xb = x4[lane + 32 * (u + 1)];
            a1 += wb.x * xb.x + wb.y * xb.y + wb.z * xb.z + wb.w * xb.w;
        }
        if (u + 2 < N4) {
            float4 wc = __ldcs(&w4[lane + 32 * (u + 2)]);
            float4 xc = x4[lane + 32 * (u + 2)];
            a2 += wc.x * xc.x + wc.y * xc.y + wc.z * xc.z + wc.w * xc.w;
        }
        if (u + 3 < N4) {
            float4 wd = __ldcs(&w4[lane + 32 * (u + 3)]);
            float4 xd = x4[lane + 32 * (u + 3)];
            a3 += wd.x * xd.x + wd.y * xd.y + wd.z * xd.z + wd.w * xd.w;
        }
    }
    float acc = (a0 + a1) + (a2 + a3);
    #pragma unroll
    for (int o = 16; o; o >>= 1) acc += __shfl_down_sync(0xFFFFFFFFu, acc, o);
    return acc;
}

// two-row interleaved dot (head): 2x in-flight weight loads
__device__ __forceinline__ void warp_dot2(const float* __restrict__ w0,
                                          const float* __restrict__ w1,
                                          const float* x, int lane,
                                          float& o0, float& o1) {
    const float4* __restrict__ a4 = (const float4*)w0;
    const float4* __restrict__ b4 = (const float4*)w1;
    const float4* x4 = (const float4*)x;
    float p0 = 0.f, p1 = 0.f, q0 = 0.f, q1 = 0.f;
    #pragma unroll
    for (int u = 0; u < 8; u += 2) {
        float4 xa = x4[lane + 32 * u];
        float4 xb = x4[lane + 32 * (u + 1)];
        float4 wa = __ldcs(&a4[lane + 32 * u]);
        float4 wb = __ldcs(&a4[lane + 32 * (u + 1)]);
        float4 va = __ldcs(&b4[lane + 32 * u]);
        float4 vb = __ldcs(&b4[lane + 32 * (u + 1)]);
        p0 += wa.x * xa.x + wa.y * xa.y + wa.z * xa.z + wa.w * xa.w;
        p1 += wb.x * xb.x + wb.y * xb.y + wb.z * xb.z + wb.w * xb.w;
        q0 += va.x * xa.x + va.y * xa.y + va.z * xa.z + va.w * xa.w;
        q1 += vb.x * xb.x + vb.y * xb.y + vb.z * xb.z + vb.w * xb.w;
    }
    float r0 = p0 + p1, r1 = q0 + q1;
    #pragma unroll
    for (int o = 16; o; o >>= 1) {
        r0 += __shfl_down_sync(0xFFFFFFFFu, r0, o);
        r1 += __shfl_down_sync(0xFFFFFFFFu, r1, o);
    }
    o0 = r0; o1 = r1;
}

__device__ __forceinline__ void cpa16(float* smem_dst, const float* g) {
    unsigned saddr = (unsigned)__cvta_generic_to_shared(smem_dst);
    asm volatile("cp.async.cg.shared.global [%0], [%1], 16;" :: "r"(saddr), "l"(g));
}

__device__ __forceinline__ const float* par_src(const P& p, int l, int a) {
    const float* st = p.state + (size_t)l * 5 * E;
    switch (a) {
        case 0:  return p.ln1w + l * E;
        case 1:  return p.ln1b + l * E;
        case 2:  return p.tmk + l * E;
        case 3:  return p.tmv + l * E;
        case 4:  return p.tmr + l * E;
        case 5:  return st + E;
        case 6:  return p.tf + l * E;
        case 7:  return p.td + l * E;
        case 8:  return st + 2 * E;
        case 9:  return st + 3 * E;
        case 10: return st + 4 * E;
        case 11: return p.ln2w + l * E;
        case 12: return p.ln2b + l * E;
        case 13: return p.ftmk + l * E;
        case 14: return p.ftmr + l * E;
        default: return st;
    }
}

__device__ __forceinline__ void prefetch_layer(const P& p, int l1, float* dst) {
    if (l1 < NL) {
        for (int t = threadIdx.x; t < NPAR * 256; t += T) {
            int a = t >> 8, i = (t & 255) << 2;
            cpa16(dst + a * E + i, par_src(p, l1, a) + i);
        }
    } else if (l1 == NL) {
        for (int t = threadIdx.x; t < 512; t += T) {
            int a = t >> 8, i = (t & 255) << 2;
            cpa16(dst + a * E + i, (a ? p.lnoutb : p.lnoutw) + i);
        }
    }
    asm volatile("cp.async.commit_group;" ::: "memory");
}

#define CP_WAIT() asm volatile("cp.async.wait_group 0;" ::: "memory")

#define SMEM_FLOATS (E + HH + 128 + 2 * NPAR * E)

__global__ void __launch_bounds__(T, 1) rwkv_kernel(P p) {
    extern __shared__ float smem[];
    float* sx   = smem;
    float* sop  = smem + E;
    float* sred = smem + E + HH;
    float* par0 = smem + E + HH + 128;

    const int tid = threadIdx.x, lane = tid & 31, warp = tid >> 5;
    const int gw = blockIdx.x * WPB + warp;
    const int NW = p.nb * WPB;
    const bool w0 = (p.ws && blockIdx.x == 0);
    float* outS = p.out + NV;
    int buf = 0;

    prefetch_layer(p, 0, par0);

    float s = 0.f, s2 = 0.f;
    for (int i = tid; i < E; i += T) { float v = p.ctx[i]; sop[i] = v; s += v; s2 += v * v; }
    block_reduce2(s, s2, sred);
    {
        float mu = s * (1.f / E);
        float rs = rsqrtf(s2 * (1.f / E) - mu * mu + 1e-5f);
        for (int i = tid; i < E; i += T)
            sx[i] = (sop[i] - mu) * rs * p.ln0w[i] + p.ln0b[i];
    }
    CP_WAIT();
    __syncthreads();

    for (int l = 0; l < NL; l++) {
        const float* pr = par0 + buf * NPAR * E;

        // ======== Stage A: combine prev FFN + LN1 + time-mix + k/v/r GEMV ========
        if (l > 0) {
            for (int i = tid; i < E; i += T) {
                float fr = 1.f / (1.f + __expf(-(g_fr4[0][i] + g_fr4[1][i] + g_fr4[2][i] + g_fr4[3][i])));
                sx[i] += fr * (g_fvp[0][i] + g_fvp[1][i] + g_fvp[2][i] + g_fvp[3][i]);
            }
        }
        s = 0.f; s2 = 0.f;
        for (int i = tid; i < E; i += T) { float v = sx[i]; s += v; s2 += v * v; }
        block_reduce2(s, s2, sred);
        {
            float mu = s * (1.f / E);
            float rs = rsqrtf(s2 * (1.f / E) - mu * mu + 1e-5f);
            for (int i = tid; i < E; i += T) {
                float xn = (sx[i] - mu) * rs * pr[0 * E + i] + pr[1 * E + i];
                float spv = pr[5 * E + i];
                float a = pr[2 * E + i], b = pr[3 * E + i], c = pr[4 * E + i];
                sop[i]         = xn * a + spv * (1.f - a);
                sop[E + i]     = xn * b + spv * (1.f - b);
                sop[2 * E + i] = xn * c + spv * (1.f - c);
                if (w0) outS[(size_t)(5 * l + 1) * E + i] = xn;
            }
        }
        __syncthreads();
        prefetch_layer(p, l + 1, par0 + (buf ^ 1) * NPAR * E);
        if (gw < 3072) {
            int m = gw >> 10, i = gw & 1023;
            const float* W = (m == 0 ? p.kw : (m == 1 ? p.vw : p.rw)) + (size_t)l * E * E;
            float acc = warp_dot<8>(W + (size_t)i * E, sop + (m << 10), lane);
            if (lane == 0) g_kvr[gw] = acc;
        }
        grid_sync(p.nb);

        // ======== Stage B: WKV + ow GEMV (quarter rows, 4096 tasks) ========
        {
            for (int i = tid; i < E; i += T) {
                float k  = g_kvr[i];
                float v  = g_kvr[E + i];
                float rr = g_kvr[2 * E + i];
                float A = pr[8 * E + i], B = pr[9 * E + i], Pp = pr[10 * E + i];
                float ww = pr[6 * E + i] + k;
                float q = fmaxf(Pp, ww);
                float e1 = __expf(Pp - q), e2 = __expf(ww - q);
                float num = e1 * A + e2 * v, den = e1 * B + e2;
                float r = 1.f / (1.f + __expf(-rr));
                sop[i] = r * num / den;
                if (w0) {
                    float ww2 = Pp + pr[7 * E + i];
                    float p2 = fmaxf(ww2, k);
                    float e1b = __expf(ww2 - p2), e2b = __expf(k - p2);
                    outS[(size_t)(5 * l + 2) * E + i] = e1b * A + e2b * v;
                    outS[(size_t)(5 * l + 3) * E + i] = e1b * B + e2b;
                    outS[(size_t)(5 * l + 4) * E + i] = p2;
                }
            }
        }
        __syncthreads();
        if (gw < 4096) {
            int q = gw & 3, i = gw >> 2;
            const float* OW = p.ow + (size_t)l * E * E;
            float acc = warp_dot<2>(OW + (size_t)i * E + q * 256, sop + q * 256, lane);
            if (lane == 0) g_op4[q][i] = acc;
        }
        grid_sync(p.nb);

        // ======== Stage C: x += ow; LN2 + chan-mix + fk (whole) / fr (quarter) ========
        for (int i = tid; i < E; i += T)
            sx[i] += g_op4[0][i] + g_op4[1][i] + g_op4[2][i] + g_op4[3][i];
        s = 0.f; s2 = 0.f;
        for (int i = tid; i < E; i += T) { float v = sx[i]; s += v; s2 += v * v; }
        block_reduce2(s, s2, sred);
        {
            float mu = s * (1.f / E);
            float rs = rsqrtf(s2 * (1.f / E) - mu * mu + 1e-5f);
            for (int i = tid; i < E; i += T) {
                float xn2 = (sx[i] - mu) * rs * pr[11 * E + i] + pr[12 * E + i];
                float sv = pr[15 * E + i];
                float a = pr[13 * E + i], b = pr[14 * E + i];
                sop[i]     = xn2 * a + sv * (1.f - a);
                sop[E + i] = xn2 * b + sv * (1.f - b);
                if (w0) outS[(size_t)(5 * l + 0) * E + i] = xn2;
            }
        }
        __syncthreads();
        {
            const float* FK = p.fkw + (size_t)l * HH * E;
            const float* FR = p.frw + (size_t)l * E * E;
            int ft = gw - 768;                       // fr tasks on warps [768, 4864)
            bool hasR = (ft >= 0 && ft < 4096);
            int rq = ft & 3, ri = ft >> 2;
            float4 rw0, rw1, rx0, rx1;
            if (hasR) {
                const float4* fr4 = (const float4*)(FR + (size_t)ri * E + rq * 256);
                const float4* fx4 = (const float4*)(sop + E + rq * 256);
                rw0 = __ldcs(&fr4[lane]); rw1 = __ldcs(&fr4[lane + 32]);
                rx0 = fx4[lane];          rx1 = fx4[lane + 32];
            }
            if (gw < 4096) {
                float acc = warp_dot<8>(FK + (size_t)gw * E, sop, lane);
                if (lane == 0) g_fk[gw] = acc;
            }
            if (hasR) {
                float a = rw0.x * rx0.x + rw0.y * rx0.y + rw0.z * rx0.z + rw0.w * rx0.w
                        + rw1.x * rx1.x + rw1.y * rx1.y + rw1.z * rx1.z + rw1.w * rx1.w;
                #pragma unroll
                for (int o = 16; o; o >>= 1) a += __shfl_down_sync(0xFFFFFFFFu, a, o);
                if (lane == 0) g_fr4[rq][ri] = a;
            }
        }
        grid_sync(p.nb);

        // ======== Stage D: kk = relu^2(fk); fv GEMV (quarter rows) ========
        for (int i = tid; i < HH; i += T) {
            float a = fmaxf(g_fk[i], 0.f);
            sop[i] = a * a;
        }
        __syncthreads();
        if (gw < 4096) {
            int c = gw & 3, i = gw >> 2;
            const float* FV = p.fvw + (size_t)l * E * HH;
            float acc = warp_dot<8>(FV + (size_t)i * HH + c * E, sop + c * E, lane);
            if (lane == 0) g_fvp[c][i] = acc;
        }
        grid_sync(p.nb);

        CP_WAIT();
        buf ^= 1;
    }

    // ======== final: combine last FFN, LN_out, head GEMV (2-row pipelined) ========
    const float* pr = par0 + buf * NPAR * E;
    for (int i = tid; i < E; i += T) {
        float fr = 1.f / (1.f + __expf(-(g_fr4[0][i] + g_fr4[1][i] + g_fr4[2][i] + g_fr4[3][i])));
        sx[i] += fr * (g_fvp[0][i] + g_fvp[1][i] + g_fvp[2][i] + g_fvp[3][i]);
    }
    s = 0.f; s2 = 0.f;
    for (int i = tid; i < E; i += T) { float v = sx[i]; s += v; s2 += v * v; }
    block_reduce2(s, s2, sred);
    {
        float mu = s * (1.f / E);
        float rs = rsqrtf(s2 * (1.f / E) - mu * mu + 1e-5f);
        for (int i = tid; i < E; i += T)
            sop[i] = (sx[i] - mu) * rs * pr[i] + pr[E + i];
    }
    __syncthreads();
    for (int t = gw; t < NV; t += 2 * NW) {
        int t2 = t + NW;
        const float* w0p = p.head + (size_t)t * E;
        const float* w1p = p.head + (size_t)(t2 < NV ? t2 : t) * E;
        float r0, r1;
        warp_dot2(w0p, w1p, sop, lane, r0, r1);
        if (lane == 0) {
            p.out[t] = r0;
            if (t2 < NV) p.out[t2] = r1;
        }
    }
}

extern "C" void kernel_launch(void* const* d_in, const int* in_sizes, int n_in,
                              void* d_out, int out_size) {
    (void)in_sizes; (void)n_in;
    P p;
    p.ctx    = (const float*)d_in[0];
    p.state  = (const float*)d_in[1];
    p.ln0w   = (const float*)d_in[2];
    p.ln0b   = (const float*)d_in[3];
    p.ln1w   = (const float*)d_in[4];
    p.ln1b   = (const float*)d_in[5];
    p.ln2w   = (const float*)d_in[6];
    p.ln2b   = (const float*)d_in[7];
    p.td     = (const float*)d_in[8];
    p.tf     = (const float*)d_in[9];
    p.tmk    = (const float*)d_in[10];
    p.tmv    = (const float*)d_in[11];
    p.tmr    = (const float*)d_in[12];
    p.kw     = (const float*)d_in[13];
    p.vw     = (const float*)d_in[14];
    p.rw     = (const float*)d_in[15];
    p.ow     = (const float*)d_in[16];
    p.ftmk   = (const float*)d_in[17];
    p.ftmr   = (const float*)d_in[18];
    p.fkw    = (const float*)d_in[19];
    p.frw    = (const float*)d_in[20];
    p.fvw    = (const float*)d_in[21];
    p.lnoutw = (const float*)d_in[22];
    p.lnoutb = (const float*)d_in[23];
    p.head   = (const float*)d_in[24];
    p.out    = (float*)d_out;

    int dev = 0;
    cudaGetDevice(&dev);
    int nsm = 0;
    cudaDeviceGetAttribute(&nsm, cudaDevAttrMultiProcessorCount, dev);
    if (nsm <= 0) nsm = 148;
    if (nsm > 256) nsm = 256;
    p.nb = nsm;
    p.ws = (out_size >= NV + 5 * NL * E) ? 1 : 0;

    cudaFuncSetAttribute(rwkv_kernel, cudaFuncAttributeMaxDynamicSharedMemorySize,
                         SMEM_FLOATS * sizeof(float));

    void* baddr = nullptr;
    cudaGetSymbolAddress(&baddr, g_bar);
    cudaMemsetAsync(baddr, 0, sizeof(unsigned int) * 2, 0);

    rwkv_kernel<<<nsm, T, SMEM_FLOATS * sizeof(float)>>>(p);
}